// round 2
// baseline (speedup 1.0000x reference)
#include <cuda_runtime.h>
#include <math.h>
#include <float.h>

#define cB 8
#define cN 4096
#define cCIN 64
#define cS 1024
#define cK 32
#define cC 128
#define cJ 5
#define cDEPTH 2
#define cH 4
#define cP (cB*cS)        // 8192 groups
#define cPK (cP*cK)       // 262144 rows
#define EPSv 1e-5f

// ---------------- scratch (static device globals; no runtime allocs) ----------------
__device__ float g_hcur[cPK*cC];        // 128MB
__device__ float g_tmp384[cPK*3*cC];    // 384MB (qkv / mlp tmp)
__device__ float g_ycat[cPK*cJ*cC];     // 640MB ([psi_j h] concat / attn out)
__device__ float g_mix[cPK*cC];         // 128MB (mix / o / mlp tmp)
__device__ float g_gin[cPK*67];
__device__ float g_gnorm[cPK*3];
__device__ float g_psis[cP*cJ*cK*cK];   // 160MB
__device__ float g_part[512*cC*2];
__device__ float g_stats[2*cC];
__device__ float g_wcat[cJ*cC*cC];
__device__ int   g_fps[cP];
__device__ int   g_knn[cPK];

// --- commit all module globals BEFORE the harness's mem checkpoint (lazy-load fix) ---
struct SymTab {
    float *hcur, *tmp384, *ycat, *mixb, *gin, *gnorm, *psis, *part, *stats, *wcat;
    int *fps, *knn;
    SymTab() {
        cudaGetSymbolAddress((void**)&hcur,   g_hcur);
        cudaGetSymbolAddress((void**)&tmp384, g_tmp384);
        cudaGetSymbolAddress((void**)&ycat,   g_ycat);
        cudaGetSymbolAddress((void**)&mixb,   g_mix);
        cudaGetSymbolAddress((void**)&gin,    g_gin);
        cudaGetSymbolAddress((void**)&gnorm,  g_gnorm);
        cudaGetSymbolAddress((void**)&psis,   g_psis);
        cudaGetSymbolAddress((void**)&part,   g_part);
        cudaGetSymbolAddress((void**)&stats,  g_stats);
        cudaGetSymbolAddress((void**)&wcat,   g_wcat);
        cudaGetSymbolAddress((void**)&fps,    g_fps);
        cudaGetSymbolAddress((void**)&knn,    g_knn);
    }
};
static SymTab g_sym;   // constructed at program start, pre-checkpoint

// ---------------- FPS: one block per batch ----------------
__global__ void fps_kernel(const float* __restrict__ xyz, int* __restrict__ fps_idx,
                           float* __restrict__ new_xyz) {
    int b = blockIdx.x, t = threadIdx.x;
    const float* X = xyz + (size_t)b*cN*3;
    float px[4], py[4], pz[4], dist[4];
#pragma unroll
    for (int i = 0; i < 4; i++) {
        int id = t + i*1024;
        px[i] = X[id*3+0]; py[i] = X[id*3+1]; pz[i] = X[id*3+2];
        dist[i] = 1e10f;
    }
    __shared__ int s_far;
    __shared__ float s_c[3];
    __shared__ unsigned long long s_red[32];
    if (t == 0) s_far = 0;
    __syncthreads();
    int lane = t & 31, wid = t >> 5;
    for (int it = 0; it < cS; it++) {
        int far = s_far;
#pragma unroll
        for (int i = 0; i < 4; i++) {
            if (t + i*1024 == far) {            // constant per-iteration index: stays in regs
                s_c[0] = px[i]; s_c[1] = py[i]; s_c[2] = pz[i];
                float* o = new_xyz + ((size_t)b*cS + it)*3;
                o[0] = px[i]; o[1] = py[i]; o[2] = pz[i];
                fps_idx[b*cS + it] = far;
            }
        }
        __syncthreads();
        float cx = s_c[0], cy = s_c[1], cz = s_c[2];
        unsigned long long best = 0ull;
#pragma unroll
        for (int i = 0; i < 4; i++) {
            float dx = px[i]-cx, dy = py[i]-cy, dz = pz[i]-cz;
            float d = dx*dx + dy*dy + dz*dz;
            dist[i] = fminf(dist[i], d);
            unsigned long long key =
                ((unsigned long long)__float_as_uint(dist[i]) << 32) |
                (unsigned)(4095 - (t + i*1024));      // tie -> smallest idx wins
            best = max(best, key);
        }
#pragma unroll
        for (int o = 16; o > 0; o >>= 1)
            best = max(best, __shfl_down_sync(0xffffffffu, best, o));
        if (lane == 0) s_red[wid] = best;
        __syncthreads();
        if (wid == 0) {
            unsigned long long v = s_red[lane];
#pragma unroll
            for (int o = 16; o > 0; o >>= 1)
                v = max(v, __shfl_down_sync(0xffffffffu, v, o));
            if (lane == 0) s_far = 4095 - (int)(v & 0xffffffffu);
        }
        __syncthreads();
    }
}

// ---------------- kNN: one block (128 thr) per group, cached per-thread minima ----------------
__global__ void knn_kernel(const float* __restrict__ xyz, const float* __restrict__ newxyz,
                           int* __restrict__ knn) {
    int p = blockIdx.x, t = threadIdx.x;
    int b = p >> 10;
    const float* X = xyz + (size_t)b*cN*3;
    __shared__ unsigned long long key[cN];
    __shared__ unsigned long long s_red[4];
    __shared__ unsigned long long s_best;
    float cx = newxyz[(size_t)p*3+0], cy = newxyz[(size_t)p*3+1], cz = newxyz[(size_t)p*3+2];
    unsigned long long lmin = ~0ull;
    for (int i = t; i < cN; i += 128) {
        float dx = X[i*3+0]-cx, dy = X[i*3+1]-cy, dz = X[i*3+2]-cz;
        float d = dx*dx + dy*dy + dz*dz;
        unsigned long long kk = ((unsigned long long)__float_as_uint(d) << 32) | (unsigned)i;
        key[i] = kk;
        lmin = min(lmin, kk);
    }
    int lane = t & 31, wid = t >> 5;
    __syncthreads();
    for (int kk = 0; kk < cK; kk++) {
        unsigned long long v = lmin;
#pragma unroll
        for (int o = 16; o > 0; o >>= 1)
            v = min(v, __shfl_xor_sync(0xffffffffu, v, o));
        if (lane == 0) s_red[wid] = v;
        __syncthreads();
        if (t == 0) {
            unsigned long long m = min(min(s_red[0], s_red[1]), min(s_red[2], s_red[3]));
            s_best = m;
            knn[(size_t)p*cK + kk] = (int)(m & 0xffffffffu);
        }
        __syncthreads();
        int idx = (int)(s_best & 0xffffffffu);
        if ((idx & 127) == t) {
            key[idx] = ~0ull;
            unsigned long long nm = ~0ull;
            for (int i = t; i < cN; i += 128) nm = min(nm, key[i]);
            lmin = nm;
        }
        __syncthreads();
    }
}

// ---------------- gather: build [gnorm(3) | points(64)] input and save gnorm ----------------
__global__ void gather_kernel(const float* __restrict__ xyz, const float* __restrict__ pts,
                              const float* __restrict__ newxyz) {
    int total = cPK*67;
    for (int i = blockIdx.x*blockDim.x + threadIdx.x; i < total; i += gridDim.x*blockDim.x) {
        int row = i / 67, col = i % 67;
        int p = row >> 5, b = p >> 10;
        int nb = g_knn[row];
        float v;
        if (col < 3) {
            v = xyz[((size_t)b*cN + nb)*3 + col] - newxyz[(size_t)p*3 + col];
            g_gnorm[(size_t)row*3 + col] = v;
        } else {
            v = pts[((size_t)b*cN + nb)*cCIN + (col-3)];
        }
        g_gin[i] = v;
    }
}

// ---------------- generic SGEMM: C[M,N] = A[M,Kd] * B, B row-major (Kd,N) or (N,Kd) if TRB --------
template<int BM, int BN, int BK, int TM, int TN, bool TRB>
__global__ __launch_bounds__((BM/TM)*(BN/TN))
void sgemm(const float* __restrict__ A, const float* __restrict__ Bm, float* __restrict__ C,
           int Kd, int Nn) {
    constexpr int NT = (BM/TM)*(BN/TN);
    constexpr int TCOL = BN/TN;
    __shared__ float As[BK][BM];
    __shared__ float Bs[BK][BN];
    int tid = threadIdx.x;
    int tx = tid % TCOL, ty = tid / TCOL;
    size_t m0 = (size_t)blockIdx.y * BM;
    int n0 = blockIdx.x * BN;
    float acc[TM][TN];
#pragma unroll
    for (int i = 0; i < TM; i++)
#pragma unroll
        for (int j = 0; j < TN; j++) acc[i][j] = 0.f;

    for (int k0 = 0; k0 < Kd; k0 += BK) {
#pragma unroll
        for (int i = tid; i < BM*BK; i += NT) {
            int mm = i / BK, kk = i % BK;
            int k = k0 + kk;
            As[kk][mm] = (k < Kd) ? A[(m0+mm)*(size_t)Kd + k] : 0.f;
        }
#pragma unroll
        for (int i = tid; i < BK*BN; i += NT) {
            int kk, nn; float v;
            if (TRB) { nn = i / BK; kk = i % BK; int k = k0+kk;
                       v = (k < Kd) ? Bm[(size_t)(n0+nn)*Kd + k] : 0.f; }
            else     { kk = i / BN; nn = i % BN; int k = k0+kk;
                       v = (k < Kd) ? Bm[(size_t)k*Nn + n0+nn] : 0.f; }
            Bs[kk][nn] = v;
        }
        __syncthreads();
#pragma unroll
        for (int kk = 0; kk < BK; kk++) {
            float a[TM], bfrag[TN];
#pragma unroll
            for (int i = 0; i < TM; i++) a[i] = As[kk][ty*TM + i];
#pragma unroll
            for (int j = 0; j < TN; j++) bfrag[j] = Bs[kk][tx*TN + j];
#pragma unroll
            for (int i = 0; i < TM; i++)
#pragma unroll
                for (int j = 0; j < TN; j++)
                    acc[i][j] = fmaf(a[i], bfrag[j], acc[i][j]);
        }
        __syncthreads();
    }
#pragma unroll
    for (int i = 0; i < TM; i++)
#pragma unroll
        for (int j = 0; j < TN; j++)
            C[(m0 + ty*TM + i)*(size_t)Nn + n0 + tx*TN + j] = acc[i][j];
}

// ---------------- BatchNorm stats (deterministic 2-stage) + apply ----------------
__global__ void bn_partial_kernel(const float* __restrict__ X, int n_ch) {
    int blk = blockIdx.x, t = threadIdx.x;
    int c = t & (n_ch - 1);
    int sub = t / n_ch;
    int rstep = 256 / n_ch;
    int rbeg = blk * (cPK/512), rend = rbeg + (cPK/512);
    float s = 0.f, s2 = 0.f;
    for (int r = rbeg + sub; r < rend; r += rstep) {
        float v = X[(size_t)r*n_ch + c];
        s += v; s2 = fmaf(v, v, s2);
    }
    __shared__ float sh[256], sh2[256];
    sh[t] = s; sh2[t] = s2;
    __syncthreads();
    if (t < n_ch) {
        float a = 0.f, a2 = 0.f;
        for (int i = t; i < 256; i += n_ch) { a += sh[i]; a2 += sh2[i]; }
        g_part[(size_t)blk*n_ch + t] = a;
        g_part[(size_t)512*n_ch + blk*n_ch + t] = a2;
    }
}
__global__ void bn_final_kernel(int n_ch) {
    int t = threadIdx.x;
    if (t < n_ch) {
        float s = 0.f, s2 = 0.f;
        for (int b = 0; b < 512; b++) {
            s  += g_part[(size_t)b*n_ch + t];
            s2 += g_part[(size_t)512*n_ch + b*n_ch + t];
        }
        float mean = s / (float)cPK;
        float var = s2 / (float)cPK - mean*mean;
        g_stats[t] = mean;
        g_stats[n_ch + t] = var;
    }
}
__global__ void bn_apply_kernel(float* __restrict__ X, const float* __restrict__ g,
                                const float* __restrict__ bv, int n_ch, int total) {
    int i = blockIdx.x*blockDim.x + threadIdx.x;
    if (i < total) {
        int c = i & (n_ch - 1);
        float v = (X[i] - g_stats[c]) * rsqrtf(g_stats[n_ch + c] + EPSv) * g[c] + bv[c];
        X[i] = fmaxf(v, 0.f);
    }
}

// ---------------- per-group geometry + psi_j (32x32 matrix polynomials) ----------------
__global__ void geom_kernel() {
    int p = blockIdx.x, t = threadIdx.x;
    int k = t >> 5, l = t & 31;
    __shared__ float s_px[32][3];
    __shared__ float s_M[32][32];
    __shared__ float s_acc[32][32];
    __shared__ float s_dinv[32];
    __shared__ float s_red[32];
    __shared__ float s_sigma;
    if (t < 32) {
        s_px[t][0] = g_gnorm[((size_t)p*32 + t)*3 + 0];
        s_px[t][1] = g_gnorm[((size_t)p*32 + t)*3 + 1];
        s_px[t][2] = g_gnorm[((size_t)p*32 + t)*3 + 2];
    }
    __syncthreads();
    float dx = s_px[k][0]-s_px[l][0], dy = s_px[k][1]-s_px[l][1], dz = s_px[k][2]-s_px[l][2];
    float dd = dx*dx + dy*dy + dz*dz;
    float sq = sqrtf(dd + 1e-12f);
    float v = sq;
#pragma unroll
    for (int o = 16; o > 0; o >>= 1) v += __shfl_xor_sync(0xffffffffu, v, o);
    if (l == 0) s_red[k] = v;
    __syncthreads();
    if (t < 32) {
        float u = s_red[t];
#pragma unroll
        for (int o = 16; o > 0; o >>= 1) u += __shfl_xor_sync(0xffffffffu, u, o);
        if (t == 0) s_sigma = u * (1.f/1024.f);
    }
    __syncthreads();
    float sg = s_sigma;
    float Ae = expf(-dd / (2.f*sg*sg + 1e-12f));
    float rs = Ae;
#pragma unroll
    for (int o = 16; o > 0; o >>= 1) rs += __shfl_xor_sync(0xffffffffu, rs, o);
    if (l == 0) s_dinv[k] = rsqrtf(rs + 1e-12f);
    __syncthreads();
    float Lkl = ((k == l) ? 1.f : 0.f) - s_dinv[k]*Ae*s_dinv[l];
    for (int j = 0; j < cJ; j++) {
        float mj = -(0.05f * (float)(1 << j)) * Lkl;
        float T = ((k == l) ? 1.f : 0.f) + mj;
        s_M[k][l] = mj;
        s_acc[k][l] = mj;
        __syncthreads();
        for (int m = 2; m <= 4; m++) {
            float vv = 0.f;
#pragma unroll
            for (int q = 0; q < 32; q++) vv += s_acc[k][q]*s_M[q][l];
            vv /= (float)m;
            __syncthreads();
            s_acc[k][l] = vv;
            __syncthreads();
            T += vv;
        }
        g_psis[(((size_t)p*cJ + j)*32 + k)*32 + l] = T;
        __syncthreads();
    }
}

// ---------------- stage1: Ycat[p, k, j*128+c] = (psi_j @ h)[k,c] ----------------
__global__ void stage1_kernel() {
    int p = blockIdx.x, t = threadIdx.x;
    __shared__ float s_h[32][128];
    __shared__ float s_psi[32][32];
    for (int i = t; i < 32*128; i += 256)
        s_h[i >> 7][i & 127] = g_hcur[(size_t)p*32*128 + i];
    int c = t & 127, khalf = t >> 7;
    for (int j = 0; j < cJ; j++) {
        __syncthreads();
        for (int i = t; i < 1024; i += 256)
            s_psi[i >> 5][i & 31] = g_psis[((size_t)p*cJ + j)*1024 + i];
        __syncthreads();
        for (int kk = 0; kk < 16; kk++) {
            int k = khalf*16 + kk;
            float v = 0.f;
#pragma unroll
            for (int q = 0; q < 32; q++) v += s_psi[k][q]*s_h[q][c];
            g_ycat[((size_t)p*32 + k)*(cJ*cC) + j*128 + c] = v;
        }
    }
}

// ---------------- Wcat[(j*128+c), d2] = alpha[d,j] * ws[d,j,c,d2] ----------------
__global__ void wcat_kernel(const float* __restrict__ ws, const float* __restrict__ alpha, int d) {
    int i = blockIdx.x*blockDim.x + threadIdx.x;
    if (i < cJ*cC*cC) {
        int row = i >> 7, d2 = i & 127;
        int j = row >> 7, c = row & 127;
        g_wcat[i] = alpha[d*cJ + j] * ws[((((size_t)d*cJ + j)*cC) + c)*cC + d2];
    }
}

// ---------------- LayerNorm: h = LN(h + f(m)) ----------------
__global__ void ln_kernel(float* __restrict__ h, const float* __restrict__ m,
                          const float* __restrict__ wbv, const float* __restrict__ g,
                          const float* __restrict__ bv, int do_relu) {
    int wp = threadIdx.x >> 5, lane = threadIdx.x & 31;
    size_t row = (size_t)blockIdx.x*8 + wp;
    float x[4];
#pragma unroll
    for (int i = 0; i < 4; i++) {
        int c = lane + 32*i;
        float a = h[row*128 + c], mm = m[row*128 + c];
        x[i] = do_relu ? (a + fmaxf(mm + wbv[c], 0.f)) : (a + mm);
    }
    float s = x[0] + x[1] + x[2] + x[3];
#pragma unroll
    for (int o = 16; o > 0; o >>= 1) s += __shfl_xor_sync(0xffffffffu, s, o);
    float mean = s * (1.f/128.f);
    float s2 = 0.f;
#pragma unroll
    for (int i = 0; i < 4; i++) { float d = x[i]-mean; s2 += d*d; }
#pragma unroll
    for (int o = 16; o > 0; o >>= 1) s2 += __shfl_xor_sync(0xffffffffu, s2, o);
    float inv = rsqrtf(s2*(1.f/128.f) + EPSv);
#pragma unroll
    for (int i = 0; i < 4; i++) {
        int c = lane + 32*i;
        h[row*128 + c] = (x[i]-mean)*inv*g[c] + bv[c];
    }
}

// ---------------- attention per group (heads=4, K=32, dh=32) ----------------
__global__ void attn_kernel() {
    int p = blockIdx.x, t = threadIdx.x;
    int hh = t >> 5, k = t & 31;
    __shared__ float s_kv[32][256];   // cols 0..127 = K, 128..255 = V
    for (int i = t; i < 32*256; i += 128) {
        int r = i >> 8, cc = i & 255;
        s_kv[r][cc] = g_tmp384[((size_t)p*32 + r)*384 + 128 + cc];
    }
    __syncthreads();
    const float* qrow = g_tmp384 + ((size_t)p*32 + k)*384 + hh*32;
    float q[32];
#pragma unroll
    for (int i = 0; i < 32; i++) q[i] = qrow[i];
    float sc[32];
    float mx = -3.4e38f;
#pragma unroll
    for (int l = 0; l < 32; l++) {
        float s = 0.f;
#pragma unroll
        for (int dq = 0; dq < 32; dq++) s += q[dq]*s_kv[l][hh*32 + dq];
        s *= 0.17677669529663688f;   // 1/sqrt(32)
        sc[l] = s;
        mx = fmaxf(mx, s);
    }
    float sum = 0.f;
#pragma unroll
    for (int l = 0; l < 32; l++) { float e = expf(sc[l]-mx); sc[l] = e; sum += e; }
    float inv = 1.f/sum;
    float* orow = g_ycat + ((size_t)p*32 + k)*128 + hh*32;
#pragma unroll
    for (int dq = 0; dq < 32; dq++) {
        float o = 0.f;
#pragma unroll
        for (int l = 0; l < 32; l++) o += sc[l]*s_kv[l][128 + hh*32 + dq];
        orow[dq] = o*inv;
    }
}

// ---------------- final max over K ----------------
__global__ void max_kernel(float* __restrict__ outp) {
    int i = blockIdx.x*blockDim.x + threadIdx.x;
    if (i < cP*cC) {
        int p = i >> 7, c = i & 127;
        float m = -3.4e38f;
#pragma unroll
        for (int k = 0; k < cK; k++)
            m = fmaxf(m, g_hcur[((size_t)p*cK + k)*cC + c]);
        outp[i] = m;
    }
}

// ================== launcher ==================
extern "C" void kernel_launch(void* const* d_in, const int* in_sizes, int n_in,
                              void* d_out, int out_size) {
    const float* xyz    = (const float*)d_in[0];
    const float* points = (const float*)d_in[1];
    const float* w1 = (const float*)d_in[2];
    const float* g1 = (const float*)d_in[3];
    const float* b1 = (const float*)d_in[4];
    const float* w2 = (const float*)d_in[5];
    const float* g2 = (const float*)d_in[6];
    const float* b2 = (const float*)d_in[7];
    const float* w3 = (const float*)d_in[8];
    const float* g3 = (const float*)d_in[9];
    const float* b3 = (const float*)d_in[10];
    const float* ws    = (const float*)d_in[11];
    const float* wb    = (const float*)d_in[12];
    const float* alpha = (const float*)d_in[13];
    const float* wqkv  = (const float*)d_in[14];
    const float* wo    = (const float*)d_in[15];
    const float* ln1g  = (const float*)d_in[16];
    const float* ln1b  = (const float*)d_in[17];
    const float* ln2g  = (const float*)d_in[18];
    const float* ln2b  = (const float*)d_in[19];

    float* outF    = (float*)d_out;
    float* newxyz  = outF;                 // (B,S,3)
    float* outFeat = outF + cB*cS*3;       // (B,S,C)

    float* hcur   = g_sym.hcur;
    float* tmp384 = g_sym.tmp384;
    float* ycat   = g_sym.ycat;
    float* mixb   = g_sym.mixb;
    float* gin    = g_sym.gin;
    float* wcat   = g_sym.wcat;
    int*   fps    = g_sym.fps;

    // 1) FPS + centroids (writes new_xyz part of d_out)
    fps_kernel<<<cB, 1024>>>(xyz, fps, newxyz);
    // 2) kNN
    knn_kernel<<<cP, 128>>>(xyz, newxyz, g_sym.knn);
    // 3) gather group features
    gather_kernel<<<(cPK*67 + 255)/256, 256>>>(xyz, points, newxyz);

    dim3 gsmall(1, cPK/128);
    // 4) MLP1: (PK,67)x(64,67)^T -> tmp384(as PKx64)
    sgemm<128,64,8,8,4,true><<<gsmall, 256>>>(gin, w1, tmp384, 67, 64);
    bn_partial_kernel<<<512, 256>>>(tmp384, 64);
    bn_final_kernel<<<1, 128>>>(64);
    bn_apply_kernel<<<(cPK*64 + 255)/256, 256>>>(tmp384, g1, b1, 64, cPK*64);
    // MLP2
    sgemm<128,64,8,8,4,true><<<gsmall, 256>>>(tmp384, w2, mixb, 64, 64);
    bn_partial_kernel<<<512, 256>>>(mixb, 64);
    bn_final_kernel<<<1, 128>>>(64);
    bn_apply_kernel<<<(cPK*64 + 255)/256, 256>>>(mixb, g2, b2, 64, cPK*64);
    // MLP3 -> hcur (PK,128)
    sgemm<128,128,8,8,8,true><<<dim3(1, cPK/128), 256>>>(mixb, w3, hcur, 64, 128);
    bn_partial_kernel<<<512, 256>>>(hcur, 128);
    bn_final_kernel<<<1, 128>>>(128);
    bn_apply_kernel<<<(cPK*128 + 255)/256, 256>>>(hcur, g3, b3, 128, cPK*128);

    // 5) per-group geometry + psis
    geom_kernel<<<cP, 1024>>>();

    // 6) depth loop
    for (int d = 0; d < cDEPTH; d++) {
        stage1_kernel<<<cP, 256>>>();
        wcat_kernel<<<(cJ*cC*cC + 255)/256, 256>>>(ws, alpha, d);
        sgemm<128,128,8,8,8,false><<<dim3(1, cPK/128), 256>>>(ycat, wcat, mixb, cJ*cC, 128);
        ln_kernel<<<cPK/8, 256>>>(hcur, mixb, wb + (size_t)d*cC, ln1g + (size_t)d*cC,
                                  ln1b + (size_t)d*cC, 1);
        sgemm<128,128,8,8,8,false><<<dim3(3, cPK/128), 256>>>(hcur, wqkv + (size_t)d*cC*3*cC,
                                                              tmp384, 128, 384);
        attn_kernel<<<cP, 128>>>();
        sgemm<128,128,8,8,8,false><<<dim3(1, cPK/128), 256>>>(ycat, wo + (size_t)d*cC*cC,
                                                              mixb, 128, 128);
        ln_kernel<<<cPK/8, 256>>>(hcur, mixb, (const float*)0, ln2g + (size_t)d*cC,
                                  ln2b + (size_t)d*cC, 0);
    }

    // 7) final max over K
    max_kernel<<<(cP*cC + 255)/256, 256>>>(outFeat);
}

// round 3
// speedup vs baseline: 1.2224x; 1.2224x over previous
#include <cuda_runtime.h>
#include <math.h>
#include <float.h>

#define cB 8
#define cN 4096
#define cCIN 64
#define cS 1024
#define cK 32
#define cC 128
#define cJ 5
#define cDEPTH 2
#define cH 4
#define cP (cB*cS)        // 8192 groups
#define cPK (cP*cK)       // 262144 rows
#define cKPAD 80          // padded MLP1 input K (67 -> 80, mult of 16)
#define EPSv 1e-5f

// ---------------- scratch (static device globals; no runtime allocs) ----------------
__device__ float g_hcur[cPK*cC];        // 128MB
__device__ float g_tmp384[cPK*3*cC];    // 384MB (qkv / mlp tmp)
__device__ float g_ycat[cPK*cJ*cC];     // 640MB (Z buffer / attn out)
__device__ float g_mix[cPK*cC];         // 128MB (mix / o / mlp tmp)
__device__ float g_gin[cPK*cKPAD];
__device__ float g_gnorm[cPK*3];
__device__ float g_psis[cP*cJ*cK*cK];   // 160MB
__device__ float g_part[512*cC*2];
__device__ float g_stats[2*cC];
__device__ float g_wcat[cC*cJ*cC];      // (128, 640) Wcat2
__device__ float g_wpad[cKPAD*64 + 64*64 + 64*cC];
__device__ int   g_fps[cP];
__device__ int   g_knn[cPK];

// --- commit all module globals BEFORE the harness's mem checkpoint (lazy-load fix) ---
struct SymTab {
    float *hcur, *tmp384, *ycat, *mixb, *gin, *gnorm, *psis, *part, *stats, *wcat, *wpad;
    int *fps, *knn;
    SymTab() {
        cudaGetSymbolAddress((void**)&hcur,   g_hcur);
        cudaGetSymbolAddress((void**)&tmp384, g_tmp384);
        cudaGetSymbolAddress((void**)&ycat,   g_ycat);
        cudaGetSymbolAddress((void**)&mixb,   g_mix);
        cudaGetSymbolAddress((void**)&gin,    g_gin);
        cudaGetSymbolAddress((void**)&gnorm,  g_gnorm);
        cudaGetSymbolAddress((void**)&psis,   g_psis);
        cudaGetSymbolAddress((void**)&part,   g_part);
        cudaGetSymbolAddress((void**)&stats,  g_stats);
        cudaGetSymbolAddress((void**)&wcat,   g_wcat);
        cudaGetSymbolAddress((void**)&wpad,   g_wpad);
        cudaGetSymbolAddress((void**)&fps,    g_fps);
        cudaGetSymbolAddress((void**)&knn,    g_knn);
    }
};
static SymTab g_sym;   // constructed at program start, pre-checkpoint

// ---------------- FPS: one block per batch ----------------
__global__ void fps_kernel(const float* __restrict__ xyz, int* __restrict__ fps_idx,
                           float* __restrict__ new_xyz) {
    int b = blockIdx.x, t = threadIdx.x;
    const float* X = xyz + (size_t)b*cN*3;
    float px[4], py[4], pz[4], dist[4];
#pragma unroll
    for (int i = 0; i < 4; i++) {
        int id = t + i*1024;
        px[i] = X[id*3+0]; py[i] = X[id*3+1]; pz[i] = X[id*3+2];
        dist[i] = 1e10f;
    }
    __shared__ int s_far;
    __shared__ float s_c[3];
    __shared__ unsigned long long s_red[32];
    if (t == 0) s_far = 0;
    __syncthreads();
    int lane = t & 31, wid = t >> 5;
    for (int it = 0; it < cS; it++) {
        int far = s_far;
#pragma unroll
        for (int i = 0; i < 4; i++) {
            if (t + i*1024 == far) {
                s_c[0] = px[i]; s_c[1] = py[i]; s_c[2] = pz[i];
                float* o = new_xyz + ((size_t)b*cS + it)*3;
                o[0] = px[i]; o[1] = py[i]; o[2] = pz[i];
                fps_idx[b*cS + it] = far;
            }
        }
        __syncthreads();
        float cx = s_c[0], cy = s_c[1], cz = s_c[2];
        unsigned long long best = 0ull;
#pragma unroll
        for (int i = 0; i < 4; i++) {
            float dx = px[i]-cx, dy = py[i]-cy, dz = pz[i]-cz;
            float d = dx*dx + dy*dy + dz*dz;
            dist[i] = fminf(dist[i], d);
            unsigned long long key =
                ((unsigned long long)__float_as_uint(dist[i]) << 32) |
                (unsigned)(4095 - (t + i*1024));
            best = max(best, key);
        }
#pragma unroll
        for (int o = 16; o > 0; o >>= 1)
            best = max(best, __shfl_down_sync(0xffffffffu, best, o));
        if (lane == 0) s_red[wid] = best;
        __syncthreads();
        if (wid == 0) {
            unsigned long long v = s_red[lane];
#pragma unroll
            for (int o = 16; o > 0; o >>= 1)
                v = max(v, __shfl_down_sync(0xffffffffu, v, o));
            if (lane == 0) s_far = 4095 - (int)(v & 0xffffffffu);
        }
        __syncthreads();
    }
}

// ---------------- kNN ----------------
__global__ void knn_kernel(const float* __restrict__ xyz, const float* __restrict__ newxyz,
                           int* __restrict__ knn) {
    int p = blockIdx.x, t = threadIdx.x;
    int b = p >> 10;
    const float* X = xyz + (size_t)b*cN*3;
    __shared__ unsigned long long key[cN];
    __shared__ unsigned long long s_red[4];
    __shared__ unsigned long long s_best;
    float cx = newxyz[(size_t)p*3+0], cy = newxyz[(size_t)p*3+1], cz = newxyz[(size_t)p*3+2];
    unsigned long long lmin = ~0ull;
    for (int i = t; i < cN; i += 128) {
        float dx = X[i*3+0]-cx, dy = X[i*3+1]-cy, dz = X[i*3+2]-cz;
        float d = dx*dx + dy*dy + dz*dz;
        unsigned long long kk = ((unsigned long long)__float_as_uint(d) << 32) | (unsigned)i;
        key[i] = kk;
        lmin = min(lmin, kk);
    }
    int lane = t & 31, wid = t >> 5;
    __syncthreads();
    for (int kk = 0; kk < cK; kk++) {
        unsigned long long v = lmin;
#pragma unroll
        for (int o = 16; o > 0; o >>= 1)
            v = min(v, __shfl_xor_sync(0xffffffffu, v, o));
        if (lane == 0) s_red[wid] = v;
        __syncthreads();
        if (t == 0) {
            unsigned long long m = min(min(s_red[0], s_red[1]), min(s_red[2], s_red[3]));
            s_best = m;
            knn[(size_t)p*cK + kk] = (int)(m & 0xffffffffu);
        }
        __syncthreads();
        int idx = (int)(s_best & 0xffffffffu);
        if ((idx & 127) == t) {
            key[idx] = ~0ull;
            unsigned long long nm = ~0ull;
            for (int i = t; i < cN; i += 128) nm = min(nm, key[i]);
            lmin = nm;
        }
        __syncthreads();
    }
}

// ---------------- gather: build [gnorm(3) | points(64) | 0-pad(13)] (stride 80) ----------------
__global__ void gather_kernel(const float* __restrict__ xyz, const float* __restrict__ pts,
                              const float* __restrict__ newxyz) {
    int total = cPK*cKPAD;
    for (int i = blockIdx.x*blockDim.x + threadIdx.x; i < total; i += gridDim.x*blockDim.x) {
        int row = i / cKPAD, col = i % cKPAD;
        int p = row >> 5, b = p >> 10;
        int nb = g_knn[row];
        float v;
        if (col < 3) {
            v = xyz[((size_t)b*cN + nb)*3 + col] - newxyz[(size_t)p*3 + col];
            g_gnorm[(size_t)row*3 + col] = v;
        } else if (col < 67) {
            v = pts[((size_t)b*cN + nb)*cCIN + (col-3)];
        } else {
            v = 0.f;
        }
        g_gin[i] = v;
    }
}

// ---------------- high-throughput SGEMM: C[M,N] = A[M,Kd] @ B[Kd,N] ----------------
// BM=128, BK=16, TM=8, 256 threads, double-buffered smem + register prefetch.
// Requires: Kd % 16 == 0, Kd % 4 == 0 (float4), N block-aligned, M % 128 == 0.
template<int BN, int TN>
__global__ __launch_bounds__(256)
void sgemm2(const float* __restrict__ A, const float* __restrict__ B,
            float* __restrict__ C, int Kd, int Nn) {
    constexpr int BM = 128, BK = 16, TM = 8;
    constexpr int TCOL = BN / TN;                 // 16
    constexpr int BLD = BN / 4;                   // float4 per B tile row
    constexpr int BNUM = (BK * BLD) / 256;        // B float4 per thread (1 or 2)
    __shared__ float As[2][BK][BM];
    __shared__ float Bs[2][BK][BN];
    const int t = threadIdx.x;
    const int tx = t % TCOL, ty = t / TCOL;
    const size_t m0 = (size_t)blockIdx.y * BM;
    const int n0 = blockIdx.x * BN;
    const int a_r = t >> 2, a_c = (t & 3) << 2;   // A: rows a_r, a_r+64; 4 cols from a_c
    const int b_r = t / BLD, b_c = (t % BLD) << 2;

    const float* Ap = A + m0 * Kd;
    float4 a0, a1, b0, b1;

    a0 = *(const float4*)(Ap + (size_t)a_r * Kd + a_c);
    a1 = *(const float4*)(Ap + (size_t)(a_r + 64) * Kd + a_c);
    b0 = *(const float4*)(B + (size_t)b_r * Nn + n0 + b_c);
    if (BNUM == 2) b1 = *(const float4*)(B + (size_t)(b_r + BK/2) * Nn + n0 + b_c);

    As[0][a_c+0][a_r] = a0.x; As[0][a_c+1][a_r] = a0.y;
    As[0][a_c+2][a_r] = a0.z; As[0][a_c+3][a_r] = a0.w;
    As[0][a_c+0][a_r+64] = a1.x; As[0][a_c+1][a_r+64] = a1.y;
    As[0][a_c+2][a_r+64] = a1.z; As[0][a_c+3][a_r+64] = a1.w;
    *(float4*)&Bs[0][b_r][b_c] = b0;
    if (BNUM == 2) *(float4*)&Bs[0][b_r + BK/2][b_c] = b1;
    __syncthreads();

    float acc[TM][TN];
#pragma unroll
    for (int i = 0; i < TM; i++)
#pragma unroll
        for (int j = 0; j < TN; j++) acc[i][j] = 0.f;

    int buf = 0;
    for (int k0 = BK; k0 < Kd; k0 += BK) {
        a0 = *(const float4*)(Ap + (size_t)a_r * Kd + k0 + a_c);
        a1 = *(const float4*)(Ap + (size_t)(a_r + 64) * Kd + k0 + a_c);
        b0 = *(const float4*)(B + (size_t)(k0 + b_r) * Nn + n0 + b_c);
        if (BNUM == 2) b1 = *(const float4*)(B + (size_t)(k0 + b_r + BK/2) * Nn + n0 + b_c);

#pragma unroll
        for (int kk = 0; kk < BK; kk++) {
            float af[TM], bf[TN];
            *(float4*)&af[0] = *(const float4*)&As[buf][kk][ty*TM];
            *(float4*)&af[4] = *(const float4*)&As[buf][kk][ty*TM + 4];
            *(float4*)&bf[0] = *(const float4*)&Bs[buf][kk][tx*TN];
            if (TN == 8) *(float4*)&bf[4] = *(const float4*)&Bs[buf][kk][tx*TN + 4];
#pragma unroll
            for (int i = 0; i < TM; i++)
#pragma unroll
                for (int j = 0; j < TN; j++)
                    acc[i][j] = fmaf(af[i], bf[j], acc[i][j]);
        }
        int nb = buf ^ 1;
        As[nb][a_c+0][a_r] = a0.x; As[nb][a_c+1][a_r] = a0.y;
        As[nb][a_c+2][a_r] = a0.z; As[nb][a_c+3][a_r] = a0.w;
        As[nb][a_c+0][a_r+64] = a1.x; As[nb][a_c+1][a_r+64] = a1.y;
        As[nb][a_c+2][a_r+64] = a1.z; As[nb][a_c+3][a_r+64] = a1.w;
        *(float4*)&Bs[nb][b_r][b_c] = b0;
        if (BNUM == 2) *(float4*)&Bs[nb][b_r + BK/2][b_c] = b1;
        __syncthreads();
        buf = nb;
    }
#pragma unroll
    for (int kk = 0; kk < BK; kk++) {
        float af[TM], bf[TN];
        *(float4*)&af[0] = *(const float4*)&As[buf][kk][ty*TM];
        *(float4*)&af[4] = *(const float4*)&As[buf][kk][ty*TM + 4];
        *(float4*)&bf[0] = *(const float4*)&Bs[buf][kk][tx*TN];
        if (TN == 8) *(float4*)&bf[4] = *(const float4*)&Bs[buf][kk][tx*TN + 4];
#pragma unroll
        for (int i = 0; i < TM; i++)
#pragma unroll
            for (int j = 0; j < TN; j++)
                acc[i][j] = fmaf(af[i], bf[j], acc[i][j]);
    }

#pragma unroll
    for (int i = 0; i < TM; i++) {
        size_t row = m0 + ty*TM + i;
#pragma unroll
        for (int j4 = 0; j4 < TN/4; j4++) {
            float4 v = make_float4(acc[i][j4*4+0], acc[i][j4*4+1],
                                   acc[i][j4*4+2], acc[i][j4*4+3]);
            *(float4*)(C + row*Nn + n0 + tx*TN + j4*4) = v;
        }
    }
}

// ---------------- weight prep: w (Nch, K) row-major -> out (Kpad, Nch), zero-padded -------
__global__ void prep_w_kernel(const float* __restrict__ w, float* __restrict__ out,
                              int K, int Nch, int Kpad) {
    int i = blockIdx.x*blockDim.x + threadIdx.x;
    if (i < Kpad*Nch) {
        int k = i / Nch, n = i % Nch;
        out[i] = (k < K) ? w[n*K + k] : 0.f;
    }
}

// ---------------- Wcat2[c, j*128+d2] = alpha[d,j] * ws[d,j,c,d2]  (shape 128 x 640) --------
__global__ void wcat_kernel(const float* __restrict__ ws, const float* __restrict__ alpha, int d) {
    int i = blockIdx.x*blockDim.x + threadIdx.x;
    if (i < cC*cJ*cC) {
        int c = i / (cJ*cC), col = i % (cJ*cC);
        int j = col >> 7, d2 = col & 127;
        g_wcat[i] = alpha[d*cJ + j] * ws[((((size_t)d*cJ + j)*cC) + c)*cC + d2];
    }
}

// ---------------- BatchNorm stats (deterministic 2-stage) + apply ----------------
__global__ void bn_partial_kernel(const float* __restrict__ X, int n_ch) {
    int blk = blockIdx.x, t = threadIdx.x;
    int c = t & (n_ch - 1);
    int sub = t / n_ch;
    int rstep = 256 / n_ch;
    int rbeg = blk * (cPK/512), rend = rbeg + (cPK/512);
    float s = 0.f, s2 = 0.f;
    for (int r = rbeg + sub; r < rend; r += rstep) {
        float v = X[(size_t)r*n_ch + c];
        s += v; s2 = fmaf(v, v, s2);
    }
    __shared__ float sh[256], sh2[256];
    sh[t] = s; sh2[t] = s2;
    __syncthreads();
    if (t < n_ch) {
        float a = 0.f, a2 = 0.f;
        for (int i = t; i < 256; i += n_ch) { a += sh[i]; a2 += sh2[i]; }
        g_part[(size_t)blk*n_ch + t] = a;
        g_part[(size_t)512*n_ch + blk*n_ch + t] = a2;
    }
}
__global__ void bn_final_kernel(int n_ch) {
    int t = threadIdx.x;
    if (t < n_ch) {
        float s = 0.f, s2 = 0.f;
        for (int b = 0; b < 512; b++) {
            s  += g_part[(size_t)b*n_ch + t];
            s2 += g_part[(size_t)512*n_ch + b*n_ch + t];
        }
        float mean = s / (float)cPK;
        float var = s2 / (float)cPK - mean*mean;
        g_stats[t] = mean;
        g_stats[n_ch + t] = var;
    }
}
__global__ void bn_apply_kernel(float* __restrict__ X, const float* __restrict__ g,
                                const float* __restrict__ bv, int n_ch, int total) {
    int i = blockIdx.x*blockDim.x + threadIdx.x;
    if (i < total) {
        int c = i & (n_ch - 1);
        float v = (X[i] - g_stats[c]) * rsqrtf(g_stats[n_ch + c] + EPSv) * g[c] + bv[c];
        X[i] = fmaxf(v, 0.f);
    }
}

// ---------------- per-group geometry + psi_j ----------------
__global__ void geom_kernel() {
    int p = blockIdx.x, t = threadIdx.x;
    int k = t >> 5, l = t & 31;
    __shared__ float s_px[32][3];
    __shared__ float s_M[32][32];
    __shared__ float s_acc[32][32];
    __shared__ float s_dinv[32];
    __shared__ float s_red[32];
    __shared__ float s_sigma;
    if (t < 32) {
        s_px[t][0] = g_gnorm[((size_t)p*32 + t)*3 + 0];
        s_px[t][1] = g_gnorm[((size_t)p*32 + t)*3 + 1];
        s_px[t][2] = g_gnorm[((size_t)p*32 + t)*3 + 2];
    }
    __syncthreads();
    float dx = s_px[k][0]-s_px[l][0], dy = s_px[k][1]-s_px[l][1], dz = s_px[k][2]-s_px[l][2];
    float dd = dx*dx + dy*dy + dz*dz;
    float sq = sqrtf(dd + 1e-12f);
    float v = sq;
#pragma unroll
    for (int o = 16; o > 0; o >>= 1) v += __shfl_xor_sync(0xffffffffu, v, o);
    if (l == 0) s_red[k] = v;
    __syncthreads();
    if (t < 32) {
        float u = s_red[t];
#pragma unroll
        for (int o = 16; o > 0; o >>= 1) u += __shfl_xor_sync(0xffffffffu, u, o);
        if (t == 0) s_sigma = u * (1.f/1024.f);
    }
    __syncthreads();
    float sg = s_sigma;
    float Ae = expf(-dd / (2.f*sg*sg + 1e-12f));
    float rs = Ae;
#pragma unroll
    for (int o = 16; o > 0; o >>= 1) rs += __shfl_xor_sync(0xffffffffu, rs, o);
    if (l == 0) s_dinv[k] = rsqrtf(rs + 1e-12f);
    __syncthreads();
    float Lkl = ((k == l) ? 1.f : 0.f) - s_dinv[k]*Ae*s_dinv[l];
    for (int j = 0; j < cJ; j++) {
        float mj = -(0.05f * (float)(1 << j)) * Lkl;
        float T = ((k == l) ? 1.f : 0.f) + mj;
        s_M[k][l] = mj;
        s_acc[k][l] = mj;
        __syncthreads();
        for (int m = 2; m <= 4; m++) {
            float vv = 0.f;
#pragma unroll
            for (int q = 0; q < 32; q++) vv += s_acc[k][q]*s_M[q][l];
            vv /= (float)m;
            __syncthreads();
            s_acc[k][l] = vv;
            __syncthreads();
            T += vv;
        }
        g_psis[(((size_t)p*cJ + j)*32 + k)*32 + l] = T;
        __syncthreads();
    }
}

// ---------------- stage2: mix[p,k,c] = sum_j (psi_j @ Z_j)[k,c], Z in g_ycat (PK x 640) ----
__global__ __launch_bounds__(256)
void stage2_kernel() {
    int p = blockIdx.x, t = threadIdx.x;
    __shared__ float s_z[32][128];
    __shared__ float s_psi[32][32];
    int c = t & 127, kh = t >> 7;
    float acc[16];
#pragma unroll
    for (int i = 0; i < 16; i++) acc[i] = 0.f;
    for (int j = 0; j < cJ; j++) {
        __syncthreads();
        for (int i = t; i < 1024; i += 256)
            s_psi[i >> 5][i & 31] = g_psis[((size_t)p*cJ + j)*1024 + i];
        for (int i = t*4; i < 4096; i += 1024) {
            int q = i >> 7, cc = i & 127;
            *(float4*)&s_z[q][cc] =
                *(const float4*)(g_ycat + (size_t)(p*32 + q)*(cJ*cC) + j*128 + cc);
        }
        __syncthreads();
#pragma unroll
        for (int kk = 0; kk < 16; kk++) {
            int k = kh*16 + kk;
            float vv = 0.f;
#pragma unroll
            for (int q = 0; q < 32; q++) vv = fmaf(s_psi[k][q], s_z[q][c], vv);
            acc[kk] += vv;
        }
    }
#pragma unroll
    for (int kk = 0; kk < 16; kk++)
        g_mix[((size_t)p*32 + kh*16 + kk)*128 + c] = acc[kk];
}

// ---------------- LayerNorm: h = LN(h + f(m)) ----------------
__global__ void ln_kernel(float* __restrict__ h, const float* __restrict__ m,
                          const float* __restrict__ wbv, const float* __restrict__ g,
                          const float* __restrict__ bv, int do_relu) {
    int wp = threadIdx.x >> 5, lane = threadIdx.x & 31;
    size_t row = (size_t)blockIdx.x*8 + wp;
    float x[4];
#pragma unroll
    for (int i = 0; i < 4; i++) {
        int c = lane + 32*i;
        float a = h[row*128 + c], mm = m[row*128 + c];
        x[i] = do_relu ? (a + fmaxf(mm + wbv[c], 0.f)) : (a + mm);
    }
    float s = x[0] + x[1] + x[2] + x[3];
#pragma unroll
    for (int o = 16; o > 0; o >>= 1) s += __shfl_xor_sync(0xffffffffu, s, o);
    float mean = s * (1.f/128.f);
    float s2 = 0.f;
#pragma unroll
    for (int i = 0; i < 4; i++) { float d = x[i]-mean; s2 += d*d; }
#pragma unroll
    for (int o = 16; o > 0; o >>= 1) s2 += __shfl_xor_sync(0xffffffffu, s2, o);
    float inv = rsqrtf(s2*(1.f/128.f) + EPSv);
#pragma unroll
    for (int i = 0; i < 4; i++) {
        int c = lane + 32*i;
        h[row*128 + c] = (x[i]-mean)*inv*g[c] + bv[c];
    }
}

// ---------------- attention per group (heads=4, K=32, dh=32) ----------------
__global__ void attn_kernel() {
    int p = blockIdx.x, t = threadIdx.x;
    int hh = t >> 5, k = t & 31;
    __shared__ float s_kv[32][256];
    for (int i = t; i < 32*256; i += 128) {
        int r = i >> 8, cc = i & 255;
        s_kv[r][cc] = g_tmp384[((size_t)p*32 + r)*384 + 128 + cc];
    }
    __syncthreads();
    const float* qrow = g_tmp384 + ((size_t)p*32 + k)*384 + hh*32;
    float q[32];
#pragma unroll
    for (int i = 0; i < 32; i++) q[i] = qrow[i];
    float sc[32];
    float mx = -3.4e38f;
#pragma unroll
    for (int l = 0; l < 32; l++) {
        float s = 0.f;
#pragma unroll
        for (int dq = 0; dq < 32; dq++) s += q[dq]*s_kv[l][hh*32 + dq];
        s *= 0.17677669529663688f;
        sc[l] = s;
        mx = fmaxf(mx, s);
    }
    float sum = 0.f;
#pragma unroll
    for (int l = 0; l < 32; l++) { float e = expf(sc[l]-mx); sc[l] = e; sum += e; }
    float inv = 1.f/sum;
    float* orow = g_ycat + ((size_t)p*32 + k)*128 + hh*32;
#pragma unroll
    for (int dq = 0; dq < 32; dq++) {
        float o = 0.f;
#pragma unroll
        for (int l = 0; l < 32; l++) o += sc[l]*s_kv[l][128 + hh*32 + dq];
        orow[dq] = o*inv;
    }
}

// ---------------- final max over K ----------------
__global__ void max_kernel(float* __restrict__ outp) {
    int i = blockIdx.x*blockDim.x + threadIdx.x;
    if (i < cP*cC) {
        int p = i >> 7, c = i & 127;
        float m = -3.4e38f;
#pragma unroll
        for (int k = 0; k < cK; k++)
            m = fmaxf(m, g_hcur[((size_t)p*cK + k)*cC + c]);
        outp[i] = m;
    }
}

// ================== launcher ==================
extern "C" void kernel_launch(void* const* d_in, const int* in_sizes, int n_in,
                              void* d_out, int out_size) {
    const float* xyz    = (const float*)d_in[0];
    const float* points = (const float*)d_in[1];
    const float* w1 = (const float*)d_in[2];
    const float* g1 = (const float*)d_in[3];
    const float* b1 = (const float*)d_in[4];
    const float* w2 = (const float*)d_in[5];
    const float* g2 = (const float*)d_in[6];
    const float* b2 = (const float*)d_in[7];
    const float* w3 = (const float*)d_in[8];
    const float* g3 = (const float*)d_in[9];
    const float* b3 = (const float*)d_in[10];
    const float* ws    = (const float*)d_in[11];
    const float* wb    = (const float*)d_in[12];
    const float* alpha = (const float*)d_in[13];
    const float* wqkv  = (const float*)d_in[14];
    const float* wo    = (const float*)d_in[15];
    const float* ln1g  = (const float*)d_in[16];
    const float* ln1b  = (const float*)d_in[17];
    const float* ln2g  = (const float*)d_in[18];
    const float* ln2b  = (const float*)d_in[19];

    float* outF    = (float*)d_out;
    float* newxyz  = outF;                 // (B,S,3)
    float* outFeat = outF + cB*cS*3;       // (B,S,C)

    float* hcur   = g_sym.hcur;
    float* tmp384 = g_sym.tmp384;
    float* ycat   = g_sym.ycat;
    float* mixb   = g_sym.mixb;
    float* gin    = g_sym.gin;
    float* wcat   = g_sym.wcat;
    float* w1p    = g_sym.wpad;
    float* w2p    = g_sym.wpad + cKPAD*64;
    float* w3p    = g_sym.wpad + cKPAD*64 + 64*64;
    int*   fps    = g_sym.fps;

    // 1) FPS + centroids
    fps_kernel<<<cB, 1024>>>(xyz, fps, newxyz);
    // 2) kNN
    knn_kernel<<<cP, 128>>>(xyz, newxyz, g_sym.knn);
    // 3) gather (stride-80 padded input)
    gather_kernel<<<(cPK*cKPAD + 255)/256, 256>>>(xyz, points, newxyz);
    // 3b) weight prep
    prep_w_kernel<<<(cKPAD*64 + 255)/256, 256>>>(w1, w1p, 67, 64, cKPAD);
    prep_w_kernel<<<(64*64 + 255)/256, 256>>>(w2, w2p, 64, 64, 64);
    prep_w_kernel<<<(64*128 + 255)/256, 256>>>(w3, w3p, 64, 128, 64);

    // 4) MLP1..3 with BN+ReLU
    sgemm2<64,4><<<dim3(1, cPK/128), 256>>>(gin, w1p, tmp384, cKPAD, 64);
    bn_partial_kernel<<<512, 256>>>(tmp384, 64);
    bn_final_kernel<<<1, 128>>>(64);
    bn_apply_kernel<<<(cPK*64 + 255)/256, 256>>>(tmp384, g1, b1, 64, cPK*64);

    sgemm2<64,4><<<dim3(1, cPK/128), 256>>>(tmp384, w2p, mixb, 64, 64);
    bn_partial_kernel<<<512, 256>>>(mixb, 64);
    bn_final_kernel<<<1, 128>>>(64);
    bn_apply_kernel<<<(cPK*64 + 255)/256, 256>>>(mixb, g2, b2, 64, cPK*64);

    sgemm2<128,8><<<dim3(1, cPK/128), 256>>>(mixb, w3p, hcur, 64, 128);
    bn_partial_kernel<<<512, 256>>>(hcur, 128);
    bn_final_kernel<<<1, 128>>>(128);
    bn_apply_kernel<<<(cPK*128 + 255)/256, 256>>>(hcur, g3, b3, 128, cPK*128);

    // 5) per-group geometry + psis
    geom_kernel<<<cP, 1024>>>();

    // 6) depth loop
    for (int d = 0; d < cDEPTH; d++) {
        // Z = hcur @ Wcat2  (PK,128)@(128,640)
        wcat_kernel<<<(cC*cJ*cC + 255)/256, 256>>>(ws, alpha, d);
        sgemm2<128,8><<<dim3(5, cPK/128), 256>>>(hcur, wcat, ycat, 128, cJ*cC);
        // mix = sum_j psi_j @ Z_j
        stage2_kernel<<<cP, 256>>>();
        ln_kernel<<<cPK/8, 256>>>(hcur, mixb, wb + (size_t)d*cC, ln1g + (size_t)d*cC,
                                  ln1b + (size_t)d*cC, 1);
        // qkv
        sgemm2<128,8><<<dim3(3, cPK/128), 256>>>(hcur, wqkv + (size_t)d*cC*3*cC,
                                                 tmp384, 128, 384);
        attn_kernel<<<cP, 128>>>();
        // o = attn_out @ wo
        sgemm2<128,8><<<dim3(1, cPK/128), 256>>>(ycat, wo + (size_t)d*cC*cC,
                                                 mixb, 128, 128);
        ln_kernel<<<cPK/8, 256>>>(hcur, mixb, (const float*)0, ln2g + (size_t)d*cC,
                                  ln2b + (size_t)d*cC, 0);
    }

    // 7) final max over K
    max_kernel<<<(cP*cC + 255)/256, 256>>>(outFeat);
}

// round 4
// speedup vs baseline: 1.5390x; 1.2590x over previous
#include <cuda_runtime.h>
#include <math.h>
#include <float.h>

#define cB 8
#define cN 4096
#define cCIN 64
#define cS 1024
#define cK 32
#define cC 128
#define cJ 5
#define cDEPTH 2
#define cH 4
#define cP (cB*cS)        // 8192 groups
#define cPK (cP*cK)       // 262144 rows
#define cKPAD 80          // padded MLP1 input K (67 -> 80, mult of 16)
#define EPSv 1e-5f

// ---------------- scratch (static device globals; no runtime allocs) ----------------
__device__ float g_hcur[cPK*cC];
__device__ float g_tmp384[cPK*3*cC];
__device__ float g_ycat[cPK*cJ*cC];
__device__ float g_mix[cPK*cC];
__device__ float g_gin[cPK*cKPAD];
__device__ float g_gnorm[cPK*3];
__device__ float g_psis[cP*cJ*cK*cK];
__device__ float g_part[512*cC*2];
__device__ float g_stats[2*cC];
__device__ float g_wcat[cC*cJ*cC];
__device__ float g_wpad[cKPAD*64 + 64*64 + 64*cC];
__device__ int   g_fps[cP];
__device__ int   g_knn[cPK];

// --- commit all module globals BEFORE the harness's mem checkpoint (lazy-load fix) ---
struct SymTab {
    float *hcur, *tmp384, *ycat, *mixb, *gin, *gnorm, *psis, *part, *stats, *wcat, *wpad;
    int *fps, *knn;
    SymTab() {
        cudaGetSymbolAddress((void**)&hcur,   g_hcur);
        cudaGetSymbolAddress((void**)&tmp384, g_tmp384);
        cudaGetSymbolAddress((void**)&ycat,   g_ycat);
        cudaGetSymbolAddress((void**)&mixb,   g_mix);
        cudaGetSymbolAddress((void**)&gin,    g_gin);
        cudaGetSymbolAddress((void**)&gnorm,  g_gnorm);
        cudaGetSymbolAddress((void**)&psis,   g_psis);
        cudaGetSymbolAddress((void**)&part,   g_part);
        cudaGetSymbolAddress((void**)&stats,  g_stats);
        cudaGetSymbolAddress((void**)&wcat,   g_wcat);
        cudaGetSymbolAddress((void**)&wpad,   g_wpad);
        cudaGetSymbolAddress((void**)&fps,    g_fps);
        cudaGetSymbolAddress((void**)&knn,    g_knn);
    }
};
static SymTab g_sym;

// ---------------- FPS ----------------
__global__ void fps_kernel(const float* __restrict__ xyz, int* __restrict__ fps_idx,
                           float* __restrict__ new_xyz) {
    int b = blockIdx.x, t = threadIdx.x;
    const float* X = xyz + (size_t)b*cN*3;
    float px[4], py[4], pz[4], dist[4];
#pragma unroll
    for (int i = 0; i < 4; i++) {
        int id = t + i*1024;
        px[i] = X[id*3+0]; py[i] = X[id*3+1]; pz[i] = X[id*3+2];
        dist[i] = 1e10f;
    }
    __shared__ int s_far;
    __shared__ float s_c[3];
    __shared__ unsigned long long s_red[32];
    if (t == 0) s_far = 0;
    __syncthreads();
    int lane = t & 31, wid = t >> 5;
    for (int it = 0; it < cS; it++) {
        int far = s_far;
#pragma unroll
        for (int i = 0; i < 4; i++) {
            if (t + i*1024 == far) {
                s_c[0] = px[i]; s_c[1] = py[i]; s_c[2] = pz[i];
                float* o = new_xyz + ((size_t)b*cS + it)*3;
                o[0] = px[i]; o[1] = py[i]; o[2] = pz[i];
                fps_idx[b*cS + it] = far;
            }
        }
        __syncthreads();
        float cx = s_c[0], cy = s_c[1], cz = s_c[2];
        unsigned long long best = 0ull;
#pragma unroll
        for (int i = 0; i < 4; i++) {
            float dx = px[i]-cx, dy = py[i]-cy, dz = pz[i]-cz;
            float d = dx*dx + dy*dy + dz*dz;
            dist[i] = fminf(dist[i], d);
            unsigned long long key =
                ((unsigned long long)__float_as_uint(dist[i]) << 32) |
                (unsigned)(4095 - (t + i*1024));
            best = max(best, key);
        }
#pragma unroll
        for (int o = 16; o > 0; o >>= 1)
            best = max(best, __shfl_down_sync(0xffffffffu, best, o));
        if (lane == 0) s_red[wid] = best;
        __syncthreads();
        if (wid == 0) {
            unsigned long long v = s_red[lane];
#pragma unroll
            for (int o = 16; o > 0; o >>= 1)
                v = max(v, __shfl_down_sync(0xffffffffu, v, o));
            if (lane == 0) s_far = 4095 - (int)(v & 0xffffffffu);
        }
        __syncthreads();
    }
}

// ---------------- kNN ----------------
__global__ void knn_kernel(const float* __restrict__ xyz, const float* __restrict__ newxyz,
                           int* __restrict__ knn) {
    int p = blockIdx.x, t = threadIdx.x;
    int b = p >> 10;
    const float* X = xyz + (size_t)b*cN*3;
    __shared__ unsigned long long key[cN];
    __shared__ unsigned long long s_red[4];
    __shared__ unsigned long long s_best;
    float cx = newxyz[(size_t)p*3+0], cy = newxyz[(size_t)p*3+1], cz = newxyz[(size_t)p*3+2];
    unsigned long long lmin = ~0ull;
    for (int i = t; i < cN; i += 128) {
        float dx = X[i*3+0]-cx, dy = X[i*3+1]-cy, dz = X[i*3+2]-cz;
        float d = dx*dx + dy*dy + dz*dz;
        unsigned long long kk = ((unsigned long long)__float_as_uint(d) << 32) | (unsigned)i;
        key[i] = kk;
        lmin = min(lmin, kk);
    }
    int lane = t & 31, wid = t >> 5;
    __syncthreads();
    for (int kk = 0; kk < cK; kk++) {
        unsigned long long v = lmin;
#pragma unroll
        for (int o = 16; o > 0; o >>= 1)
            v = min(v, __shfl_xor_sync(0xffffffffu, v, o));
        if (lane == 0) s_red[wid] = v;
        __syncthreads();
        if (t == 0) {
            unsigned long long m = min(min(s_red[0], s_red[1]), min(s_red[2], s_red[3]));
            s_best = m;
            knn[(size_t)p*cK + kk] = (int)(m & 0xffffffffu);
        }
        __syncthreads();
        int idx = (int)(s_best & 0xffffffffu);
        if ((idx & 127) == t) {
            key[idx] = ~0ull;
            unsigned long long nm = ~0ull;
            for (int i = t; i < cN; i += 128) nm = min(nm, key[i]);
            lmin = nm;
        }
        __syncthreads();
    }
}

// ---------------- gather ----------------
__global__ void gather_kernel(const float* __restrict__ xyz, const float* __restrict__ pts,
                              const float* __restrict__ newxyz) {
    int total = cPK*cKPAD;
    for (int i = blockIdx.x*blockDim.x + threadIdx.x; i < total; i += gridDim.x*blockDim.x) {
        int row = i / cKPAD, col = i % cKPAD;
        int p = row >> 5, b = p >> 10;
        int nb = g_knn[row];
        float v;
        if (col < 3) {
            v = xyz[((size_t)b*cN + nb)*3 + col] - newxyz[(size_t)p*3 + col];
            g_gnorm[(size_t)row*3 + col] = v;
        } else if (col < 67) {
            v = pts[((size_t)b*cN + nb)*cCIN + (col-3)];
        } else {
            v = 0.f;
        }
        g_gin[i] = v;
    }
}

// ---------------- TF32 tensor-core GEMM ----------------
__device__ __forceinline__ unsigned f2tf(float x) {
    unsigned r;
    asm("cvt.rna.tf32.f32 %0, %1;" : "=r"(r) : "f"(x));
    return r;
}
__device__ __forceinline__ void mma_tf32(float* c, const unsigned* a, const unsigned* b) {
    asm volatile(
        "mma.sync.aligned.m16n8k8.row.col.f32.tf32.tf32.f32 "
        "{%0,%1,%2,%3}, {%4,%5,%6,%7}, {%8,%9}, {%0,%1,%2,%3};"
        : "+f"(c[0]), "+f"(c[1]), "+f"(c[2]), "+f"(c[3])
        : "r"(a[0]), "r"(a[1]), "r"(a[2]), "r"(a[3]), "r"(b[0]), "r"(b[1]));
}

// C[M,N] = A[M,Kd] @ B[Kd,N]; M%128==0, Kd%16==0, N tiles of BN.
// 8 warps (4M x 2N); warp tile 32 x BN/2; m16n8k8 TF32 fragments.
template<int BN>
__global__ __launch_bounds__(256)
void tgemm(const float* __restrict__ A, const float* __restrict__ B,
           float* __restrict__ C, int Kd, int Nn) {
    constexpr int BM = 128, BK = 16;
    constexpr int AS = 20;            // A smem stride (conflict-free)
    constexpr int BNp = BN + 4;       // B smem stride (conflict-free)
    constexpr int NT = BN / 16;       // n-tiles of 8 per warp
    constexpr int NB4 = BK * BN / 4;  // float4 count in B tile
    __shared__ unsigned As[2][BM * AS];
    __shared__ unsigned Bs[2][BK * BNp];

    const int t = threadIdx.x, lane = t & 31, w = t >> 5;
    const int wm = (w & 3) * 32;            // warp M origin
    const int wn = (w >> 2) * (BN / 2);     // warp N origin
    const size_t m0 = (size_t)blockIdx.y * BM;
    const int n0 = blockIdx.x * BN;
    const int g = lane >> 2, tg = lane & 3;

    const float* Ap = A + m0 * Kd;
    const int ar = t >> 1, ac = (t & 1) * 8;

    float4 ra0, ra1, rb0, rb1;
    // initial global -> smem
    ra0 = *(const float4*)(Ap + (size_t)ar * Kd + ac);
    ra1 = *(const float4*)(Ap + (size_t)ar * Kd + ac + 4);
    {
        int i = t, r = i / (BN/4), c = (i % (BN/4)) * 4;
        rb0 = *(const float4*)(B + (size_t)r * Nn + n0 + c);
        if (NB4 == 512) {
            int i2 = t + 256, r2 = i2 / (BN/4), c2 = (i2 % (BN/4)) * 4;
            rb1 = *(const float4*)(B + (size_t)r2 * Nn + n0 + c2);
        }
    }
    {
        unsigned* dstA = &As[0][ar * AS + ac];
        dstA[0]=f2tf(ra0.x); dstA[1]=f2tf(ra0.y); dstA[2]=f2tf(ra0.z); dstA[3]=f2tf(ra0.w);
        dstA[4]=f2tf(ra1.x); dstA[5]=f2tf(ra1.y); dstA[6]=f2tf(ra1.z); dstA[7]=f2tf(ra1.w);
        int i = t, r = i / (BN/4), c = (i % (BN/4)) * 4;
        unsigned* dstB = &Bs[0][r * BNp + c];
        dstB[0]=f2tf(rb0.x); dstB[1]=f2tf(rb0.y); dstB[2]=f2tf(rb0.z); dstB[3]=f2tf(rb0.w);
        if (NB4 == 512) {
            int i2 = t + 256, r2 = i2 / (BN/4), c2 = (i2 % (BN/4)) * 4;
            unsigned* dB2 = &Bs[0][r2 * BNp + c2];
            dB2[0]=f2tf(rb1.x); dB2[1]=f2tf(rb1.y); dB2[2]=f2tf(rb1.z); dB2[3]=f2tf(rb1.w);
        }
    }
    __syncthreads();

    float acc[2][NT][4];
#pragma unroll
    for (int i = 0; i < 2; i++)
#pragma unroll
        for (int j = 0; j < NT; j++)
#pragma unroll
            for (int q = 0; q < 4; q++) acc[i][j][q] = 0.f;

    int buf = 0;
    for (int k0 = BK; k0 <= Kd; k0 += BK) {
        bool more = (k0 < Kd);
        if (more) {
            ra0 = *(const float4*)(Ap + (size_t)ar * Kd + k0 + ac);
            ra1 = *(const float4*)(Ap + (size_t)ar * Kd + k0 + ac + 4);
            int i = t, r = i / (BN/4), c = (i % (BN/4)) * 4;
            rb0 = *(const float4*)(B + (size_t)(k0 + r) * Nn + n0 + c);
            if (NB4 == 512) {
                int i2 = t + 256, r2 = i2 / (BN/4), c2 = (i2 % (BN/4)) * 4;
                rb1 = *(const float4*)(B + (size_t)(k0 + r2) * Nn + n0 + c2);
            }
        }
#pragma unroll
        for (int ks = 0; ks < 2; ks++) {
            const int kb = ks * 8;
            unsigned af[2][4];
#pragma unroll
            for (int mt = 0; mt < 2; mt++) {
                int r = wm + mt*16 + g;
                af[mt][0] = As[buf][(r    ) * AS + kb + tg];
                af[mt][1] = As[buf][(r + 8) * AS + kb + tg];
                af[mt][2] = As[buf][(r    ) * AS + kb + tg + 4];
                af[mt][3] = As[buf][(r + 8) * AS + kb + tg + 4];
            }
            unsigned bf[NT][2];
#pragma unroll
            for (int j = 0; j < NT; j++) {
                int cb = wn + j*8 + g;
                bf[j][0] = Bs[buf][(kb     + tg) * BNp + cb];
                bf[j][1] = Bs[buf][(kb + 4 + tg) * BNp + cb];
            }
#pragma unroll
            for (int mt = 0; mt < 2; mt++)
#pragma unroll
                for (int j = 0; j < NT; j++)
                    mma_tf32(acc[mt][j], af[mt], bf[j]);
        }
        if (more) {
            int nb = buf ^ 1;
            unsigned* dstA = &As[nb][ar * AS + ac];
            dstA[0]=f2tf(ra0.x); dstA[1]=f2tf(ra0.y); dstA[2]=f2tf(ra0.z); dstA[3]=f2tf(ra0.w);
            dstA[4]=f2tf(ra1.x); dstA[5]=f2tf(ra1.y); dstA[6]=f2tf(ra1.z); dstA[7]=f2tf(ra1.w);
            int i = t, r = i / (BN/4), c = (i % (BN/4)) * 4;
            unsigned* dstB = &Bs[nb][r * BNp + c];
            dstB[0]=f2tf(rb0.x); dstB[1]=f2tf(rb0.y); dstB[2]=f2tf(rb0.z); dstB[3]=f2tf(rb0.w);
            if (NB4 == 512) {
                int i2 = t + 256, r2 = i2 / (BN/4), c2 = (i2 % (BN/4)) * 4;
                unsigned* dB2 = &Bs[nb][r2 * BNp + c2];
                dB2[0]=f2tf(rb1.x); dB2[1]=f2tf(rb1.y); dB2[2]=f2tf(rb1.z); dB2[3]=f2tf(rb1.w);
            }
            __syncthreads();
            buf = nb;
        }
    }

#pragma unroll
    for (int mt = 0; mt < 2; mt++) {
#pragma unroll
        for (int j = 0; j < NT; j++) {
            int col = n0 + wn + j*8 + tg*2;
            size_t r0 = m0 + wm + mt*16 + g;
            *(float2*)(C + r0 * Nn + col)       = make_float2(acc[mt][j][0], acc[mt][j][1]);
            *(float2*)(C + (r0 + 8) * Nn + col) = make_float2(acc[mt][j][2], acc[mt][j][3]);
        }
    }
}

// ---------------- weight prep: w (Nch, K) row-major -> out (Kpad, Nch) ----------------
__global__ void prep_w_kernel(const float* __restrict__ w, float* __restrict__ out,
                              int K, int Nch, int Kpad) {
    int i = blockIdx.x*blockDim.x + threadIdx.x;
    if (i < Kpad*Nch) {
        int k = i / Nch, n = i % Nch;
        out[i] = (k < K) ? w[n*K + k] : 0.f;
    }
}

// ---------------- Wcat2[c, j*128+d2] = alpha[d,j]*ws[d,j,c,d2] ----------------
__global__ void wcat_kernel(const float* __restrict__ ws, const float* __restrict__ alpha, int d) {
    int i = blockIdx.x*blockDim.x + threadIdx.x;
    if (i < cC*cJ*cC) {
        int c = i / (cJ*cC), col = i % (cJ*cC);
        int j = col >> 7, d2 = col & 127;
        g_wcat[i] = alpha[d*cJ + j] * ws[((((size_t)d*cJ + j)*cC) + c)*cC + d2];
    }
}

// ---------------- BatchNorm (deterministic 2-stage) + apply ----------------
__global__ void bn_partial_kernel(const float* __restrict__ X, int n_ch) {
    int blk = blockIdx.x, t = threadIdx.x;
    int c = t & (n_ch - 1);
    int sub = t / n_ch;
    int rstep = 256 / n_ch;
    int rbeg = blk * (cPK/512), rend = rbeg + (cPK/512);
    float s = 0.f, s2 = 0.f;
    for (int r = rbeg + sub; r < rend; r += rstep) {
        float v = X[(size_t)r*n_ch + c];
        s += v; s2 = fmaf(v, v, s2);
    }
    __shared__ float sh[256], sh2[256];
    sh[t] = s; sh2[t] = s2;
    __syncthreads();
    if (t < n_ch) {
        float a = 0.f, a2 = 0.f;
        for (int i = t; i < 256; i += n_ch) { a += sh[i]; a2 += sh2[i]; }
        g_part[(size_t)blk*n_ch + t] = a;
        g_part[(size_t)512*n_ch + blk*n_ch + t] = a2;
    }
}
__global__ void bn_final_kernel(int n_ch) {
    int t = threadIdx.x;
    if (t < n_ch) {
        float s = 0.f, s2 = 0.f;
        for (int b = 0; b < 512; b++) {
            s  += g_part[(size_t)b*n_ch + t];
            s2 += g_part[(size_t)512*n_ch + b*n_ch + t];
        }
        float mean = s / (float)cPK;
        float var = s2 / (float)cPK - mean*mean;
        g_stats[t] = mean;
        g_stats[n_ch + t] = var;
    }
}
__global__ void bn_apply_kernel(float* __restrict__ X, const float* __restrict__ g,
                                const float* __restrict__ bv, int n_ch, int total) {
    int i = blockIdx.x*blockDim.x + threadIdx.x;
    if (i < total) {
        int c = i & (n_ch - 1);
        float v = (X[i] - g_stats[c]) * rsqrtf(g_stats[n_ch + c] + EPSv) * g[c] + bv[c];
        X[i] = fmaxf(v, 0.f);
    }
}

// ---------------- per-group geometry + psi_j ----------------
__global__ void geom_kernel() {
    int p = blockIdx.x, t = threadIdx.x;
    int k = t >> 5, l = t & 31;
    __shared__ float s_px[32][3];
    __shared__ float s_M[32][32];
    __shared__ float s_acc[32][32];
    __shared__ float s_dinv[32];
    __shared__ float s_red[32];
    __shared__ float s_sigma;
    if (t < 32) {
        s_px[t][0] = g_gnorm[((size_t)p*32 + t)*3 + 0];
        s_px[t][1] = g_gnorm[((size_t)p*32 + t)*3 + 1];
        s_px[t][2] = g_gnorm[((size_t)p*32 + t)*3 + 2];
    }
    __syncthreads();
    float dx = s_px[k][0]-s_px[l][0], dy = s_px[k][1]-s_px[l][1], dz = s_px[k][2]-s_px[l][2];
    float dd = dx*dx + dy*dy + dz*dz;
    float sq = sqrtf(dd + 1e-12f);
    float v = sq;
#pragma unroll
    for (int o = 16; o > 0; o >>= 1) v += __shfl_xor_sync(0xffffffffu, v, o);
    if (l == 0) s_red[k] = v;
    __syncthreads();
    if (t < 32) {
        float u = s_red[t];
#pragma unroll
        for (int o = 16; o > 0; o >>= 1) u += __shfl_xor_sync(0xffffffffu, u, o);
        if (t == 0) s_sigma = u * (1.f/1024.f);
    }
    __syncthreads();
    float sg = s_sigma;
    float Ae = expf(-dd / (2.f*sg*sg + 1e-12f));
    float rs = Ae;
#pragma unroll
    for (int o = 16; o > 0; o >>= 1) rs += __shfl_xor_sync(0xffffffffu, rs, o);
    if (l == 0) s_dinv[k] = rsqrtf(rs + 1e-12f);
    __syncthreads();
    float Lkl = ((k == l) ? 1.f : 0.f) - s_dinv[k]*Ae*s_dinv[l];
    for (int j = 0; j < cJ; j++) {
        float mj = -(0.05f * (float)(1 << j)) * Lkl;
        float T = ((k == l) ? 1.f : 0.f) + mj;
        s_M[k][l] = mj;
        s_acc[k][l] = mj;
        __syncthreads();
        for (int m = 2; m <= 4; m++) {
            float vv = 0.f;
#pragma unroll
            for (int q = 0; q < 32; q++) vv += s_acc[k][q]*s_M[q][l];
            vv /= (float)m;
            __syncthreads();
            s_acc[k][l] = vv;
            __syncthreads();
            T += vv;
        }
        g_psis[(((size_t)p*cJ + j)*32 + k)*32 + l] = T;
        __syncthreads();
    }
}

// ---------------- stage2: mix = sum_j psi_j @ Z_j ----------------
__global__ __launch_bounds__(256)
void stage2_kernel() {
    int p = blockIdx.x, t = threadIdx.x;
    __shared__ float s_z[32][128];
    __shared__ float s_psi[32][32];
    int c = t & 127, kh = t >> 7;
    float acc[16];
#pragma unroll
    for (int i = 0; i < 16; i++) acc[i] = 0.f;
    for (int j = 0; j < cJ; j++) {
        __syncthreads();
        for (int i = t; i < 1024; i += 256)
            s_psi[i >> 5][i & 31] = g_psis[((size_t)p*cJ + j)*1024 + i];
        for (int i = t*4; i < 4096; i += 1024) {
            int q = i >> 7, cc = i & 127;
            *(float4*)&s_z[q][cc] =
                *(const float4*)(g_ycat + (size_t)(p*32 + q)*(cJ*cC) + j*128 + cc);
        }
        __syncthreads();
#pragma unroll
        for (int kk = 0; kk < 16; kk++) {
            int k = kh*16 + kk;
            float vv = 0.f;
#pragma unroll
            for (int q = 0; q < 32; q++) vv = fmaf(s_psi[k][q], s_z[q][c], vv);
            acc[kk] += vv;
        }
    }
#pragma unroll
    for (int kk = 0; kk < 16; kk++)
        g_mix[((size_t)p*32 + kh*16 + kk)*128 + c] = acc[kk];
}

// ---------------- LayerNorm ----------------
__global__ void ln_kernel(float* __restrict__ h, const float* __restrict__ m,
                          const float* __restrict__ wbv, const float* __restrict__ g,
                          const float* __restrict__ bv, int do_relu) {
    int wp = threadIdx.x >> 5, lane = threadIdx.x & 31;
    size_t row = (size_t)blockIdx.x*8 + wp;
    float x[4];
#pragma unroll
    for (int i = 0; i < 4; i++) {
        int c = lane + 32*i;
        float a = h[row*128 + c], mm = m[row*128 + c];
        x[i] = do_relu ? (a + fmaxf(mm + wbv[c], 0.f)) : (a + mm);
    }
    float s = x[0] + x[1] + x[2] + x[3];
#pragma unroll
    for (int o = 16; o > 0; o >>= 1) s += __shfl_xor_sync(0xffffffffu, s, o);
    float mean = s * (1.f/128.f);
    float s2 = 0.f;
#pragma unroll
    for (int i = 0; i < 4; i++) { float d = x[i]-mean; s2 += d*d; }
#pragma unroll
    for (int o = 16; o > 0; o >>= 1) s2 += __shfl_xor_sync(0xffffffffu, s2, o);
    float inv = rsqrtf(s2*(1.f/128.f) + EPSv);
#pragma unroll
    for (int i = 0; i < 4; i++) {
        int c = lane + 32*i;
        h[row*128 + c] = (x[i]-mean)*inv*g[c] + bv[c];
    }
}

// ---------------- attention ----------------
__global__ void attn_kernel() {
    int p = blockIdx.x, t = threadIdx.x;
    int hh = t >> 5, k = t & 31;
    __shared__ float s_kv[32][256];
    for (int i = t; i < 32*256; i += 128) {
        int r = i >> 8, cc = i & 255;
        s_kv[r][cc] = g_tmp384[((size_t)p*32 + r)*384 + 128 + cc];
    }
    __syncthreads();
    const float* qrow = g_tmp384 + ((size_t)p*32 + k)*384 + hh*32;
    float q[32];
#pragma unroll
    for (int i = 0; i < 32; i++) q[i] = qrow[i];
    float sc[32];
    float mx = -3.4e38f;
#pragma unroll
    for (int l = 0; l < 32; l++) {
        float s = 0.f;
#pragma unroll
        for (int dq = 0; dq < 32; dq++) s += q[dq]*s_kv[l][hh*32 + dq];
        s *= 0.17677669529663688f;
        sc[l] = s;
        mx = fmaxf(mx, s);
    }
    float sum = 0.f;
#pragma unroll
    for (int l = 0; l < 32; l++) { float e = expf(sc[l]-mx); sc[l] = e; sum += e; }
    float inv = 1.f/sum;
    float* orow = g_ycat + ((size_t)p*32 + k)*128 + hh*32;
#pragma unroll
    for (int dq = 0; dq < 32; dq++) {
        float o = 0.f;
#pragma unroll
        for (int l = 0; l < 32; l++) o += sc[l]*s_kv[l][128 + hh*32 + dq];
        orow[dq] = o*inv;
    }
}

// ---------------- final max over K ----------------
__global__ void max_kernel(float* __restrict__ outp) {
    int i = blockIdx.x*blockDim.x + threadIdx.x;
    if (i < cP*cC) {
        int p = i >> 7, c = i & 127;
        float m = -3.4e38f;
#pragma unroll
        for (int k = 0; k < cK; k++)
            m = fmaxf(m, g_hcur[((size_t)p*cK + k)*cC + c]);
        outp[i] = m;
    }
}

// ================== launcher ==================
extern "C" void kernel_launch(void* const* d_in, const int* in_sizes, int n_in,
                              void* d_out, int out_size) {
    const float* xyz    = (const float*)d_in[0];
    const float* points = (const float*)d_in[1];
    const float* w1 = (const float*)d_in[2];
    const float* g1 = (const float*)d_in[3];
    const float* b1 = (const float*)d_in[4];
    const float* w2 = (const float*)d_in[5];
    const float* g2 = (const float*)d_in[6];
    const float* b2 = (const float*)d_in[7];
    const float* w3 = (const float*)d_in[8];
    const float* g3 = (const float*)d_in[9];
    const float* b3 = (const float*)d_in[10];
    const float* ws    = (const float*)d_in[11];
    const float* wb    = (const float*)d_in[12];
    const float* alpha = (const float*)d_in[13];
    const float* wqkv  = (const float*)d_in[14];
    const float* wo    = (const float*)d_in[15];
    const float* ln1g  = (const float*)d_in[16];
    const float* ln1b  = (const float*)d_in[17];
    const float* ln2g  = (const float*)d_in[18];
    const float* ln2b  = (const float*)d_in[19];

    float* outF    = (float*)d_out;
    float* newxyz  = outF;
    float* outFeat = outF + cB*cS*3;

    float* hcur   = g_sym.hcur;
    float* tmp384 = g_sym.tmp384;
    float* ycat   = g_sym.ycat;
    float* mixb   = g_sym.mixb;
    float* gin    = g_sym.gin;
    float* wcat   = g_sym.wcat;
    float* w1p    = g_sym.wpad;
    float* w2p    = g_sym.wpad + cKPAD*64;
    float* w3p    = g_sym.wpad + cKPAD*64 + 64*64;
    int*   fps    = g_sym.fps;

    fps_kernel<<<cB, 1024>>>(xyz, fps, newxyz);
    knn_kernel<<<cP, 128>>>(xyz, newxyz, g_sym.knn);
    gather_kernel<<<(cPK*cKPAD + 255)/256, 256>>>(xyz, points, newxyz);
    prep_w_kernel<<<(cKPAD*64 + 255)/256, 256>>>(w1, w1p, 67, 64, cKPAD);
    prep_w_kernel<<<(64*64 + 255)/256, 256>>>(w2, w2p, 64, 64, 64);
    prep_w_kernel<<<(64*128 + 255)/256, 256>>>(w3, w3p, 64, 128, 64);

    // MLP1..3 with BN+ReLU (tensor-core TF32 GEMMs)
    tgemm<64><<<dim3(1, cPK/128), 256>>>(gin, w1p, tmp384, cKPAD, 64);
    bn_partial_kernel<<<512, 256>>>(tmp384, 64);
    bn_final_kernel<<<1, 128>>>(64);
    bn_apply_kernel<<<(cPK*64 + 255)/256, 256>>>(tmp384, g1, b1, 64, cPK*64);

    tgemm<64><<<dim3(1, cPK/128), 256>>>(tmp384, w2p, mixb, 64, 64);
    bn_partial_kernel<<<512, 256>>>(mixb, 64);
    bn_final_kernel<<<1, 128>>>(64);
    bn_apply_kernel<<<(cPK*64 + 255)/256, 256>>>(mixb, g2, b2, 64, cPK*64);

    tgemm<128><<<dim3(1, cPK/128), 256>>>(mixb, w3p, hcur, 64, 128);
    bn_partial_kernel<<<512, 256>>>(hcur, 128);
    bn_final_kernel<<<1, 128>>>(128);
    bn_apply_kernel<<<(cPK*128 + 255)/256, 256>>>(hcur, g3, b3, 128, cPK*128);

    geom_kernel<<<cP, 1024>>>();

    for (int d = 0; d < cDEPTH; d++) {
        wcat_kernel<<<(cC*cJ*cC + 255)/256, 256>>>(ws, alpha, d);
        tgemm<128><<<dim3(5, cPK/128), 256>>>(hcur, wcat, ycat, 128, cJ*cC);
        stage2_kernel<<<cP, 256>>>();
        ln_kernel<<<cPK/8, 256>>>(hcur, mixb, wb + (size_t)d*cC, ln1g + (size_t)d*cC,
                                  ln1b + (size_t)d*cC, 1);
        tgemm<128><<<dim3(3, cPK/128), 256>>>(hcur, wqkv + (size_t)d*cC*3*cC,
                                              tmp384, 128, 384);
        attn_kernel<<<cP, 128>>>();
        tgemm<128><<<dim3(1, cPK/128), 256>>>(ycat, wo + (size_t)d*cC*cC,
                                              mixb, 128, 128);
        ln_kernel<<<cPK/8, 256>>>(hcur, mixb, (const float*)0, ln2g + (size_t)d*cC,
                                  ln2b + (size_t)d*cC, 0);
    }

    max_kernel<<<(cP*cC + 255)/256, 256>>>(outFeat);
}